// round 5
// baseline (speedup 1.0000x reference)
#include <cuda_runtime.h>
#include <cuda_fp16.h>
#include <cstdint>
#include <math.h>

// Problem dims
#define B_ROWS 8192
#define N_COLS 512
#define M_MIN  1024
#define OUT_N  256
#define K_TOT  4096   // 512*6 + 1024

// ---------------- device scratch (static, no allocation) ----------------
__device__ float g_psum[64 * 512];
__device__ float g_psumsq[64 * 512];
__device__ float g_s[512];
__device__ float g_dq[6 * 512];           // [q][n]
__device__ uint32_t g_minidx[M_MIN];      // packed (off2<<16)|off1, off = q*512+n
__device__ __align__(16) __half g_wT[(size_t)OUT_N * K_TOT];        // 2 MB  (B^T, [256,4096] K-major)
__device__ __align__(16) __half g_feat[(size_t)B_ROWS * K_TOT];     // 64 MB (A, [8192,4096] K-major)

__constant__ float QCOEF[5] = {-3.0f, -0.834f, -0.248f, 0.248f, 0.834f};

// ---------------- helpers ----------------
__device__ __forceinline__ uint32_t smem_u32(const void* p) {
    uint32_t a;
    asm("{ .reg .u64 t; cvta.to.shared.u64 t, %1; cvt.u32.u64 %0, t; }"
        : "=r"(a) : "l"(p));
    return a;
}

// ---------------- stage 1: column statistics (deterministic two-pass) ----------------
__global__ void __launch_bounds__(512) k_stats(const float* __restrict__ x) {
    int col = threadIdx.x;
    int rb  = blockIdx.x * 128;
    const float* xp = x + (size_t)rb * 512 + col;
    float s = 0.f, ss = 0.f;
#pragma unroll 8
    for (int r = 0; r < 128; r++) {
        float v = xp[(size_t)r * 512];
        s += v;
        ss = fmaf(v, v, ss);
    }
    g_psum[blockIdx.x * 512 + col]   = s;
    g_psumsq[blockIdx.x * 512 + col] = ss;
}

__global__ void __launch_bounds__(512) k_finalize(const float* __restrict__ beta,
                                                  const float* __restrict__ gamma) {
    int n = threadIdx.x;
    float s = 0.f, ss = 0.f;
    for (int b = 0; b < 64; b++) {           // fixed order -> deterministic
        s  += g_psum[b * 512 + n];
        ss += g_psumsq[b * 512 + n];
    }
    float mean = s * (1.f / 8192.f);
    float var  = ss * (1.f / 8192.f) - mean * mean;
    float sc   = gamma[n] / sqrtf(var + 0.001f);
    float c    = beta[n] - mean * sc;        // normed = sc*x + c
    g_s[n]  = sc;
    g_dq[n] = c;                              // q = 0 (base relu)
#pragma unroll
    for (int q = 0; q < 5; q++)
        g_dq[(q + 1) * 512 + n] = c + beta[n] - gamma[n] * fmaf(QCOEF[q], var, mean);
}

// ---------------- stage 2: pack min-feature gather indices (dtype-robust) ----------------
// chosen_index may arrive as int64 OR int32 (JAX x64-disabled silently downcasts).
// Column 0 is arange(M): int32-view element 10 == 1 iff int64 layout (low word of
// row-1 cnt), == 2 iff int32 layout (row-2 cnt). Deterministic on the fixed input.
__global__ void __launch_bounds__(1024) k_packidx(const void* __restrict__ ci_raw) {
    int m = threadIdx.x;
    const int* p32 = (const int*)ci_raw;
    bool is64 = (p32[10] == 1) && (p32[11] == 0);
    uint32_t n1, q1, n2, q2;
    if (is64) {
        const long long* e = (const long long*)ci_raw + (size_t)m * 5;
        n1 = (uint32_t)e[1]; q1 = (uint32_t)e[2];
        n2 = (uint32_t)e[3]; q2 = (uint32_t)e[4];
    } else {
        const int* e = p32 + (size_t)m * 5;
        n1 = (uint32_t)e[1]; q1 = (uint32_t)e[2];
        n2 = (uint32_t)e[3]; q2 = (uint32_t)e[4];
    }
    uint32_t off1 = q1 * 512u + n1;
    uint32_t off2 = q2 * 512u + n2;
    g_minidx[m] = (off2 << 16) | off1;
}

// ---------------- stage 3: w -> wT fp16, K-permuted (j = q*512+n for j<3072) ----------------
__global__ void __launch_bounds__(256) k_wprep(const float* __restrict__ w) {
    __shared__ float tile[32][33];
    int j0 = blockIdx.x * 32, o0 = blockIdx.y * 32;
    int tx = threadIdx.x, ty = threadIdx.y;
    for (int i = ty; i < 32; i += 8) {
        int j = j0 + i;
        int k = (j < 3072) ? ((j & 511) * 6 + (j >> 9)) : j;   // back to original row order
        tile[i][tx] = w[(size_t)k * 256 + o0 + tx];
    }
    __syncthreads();
    for (int i = ty; i < 32; i += 8)
        g_wT[(size_t)(o0 + i) * K_TOT + j0 + tx] = __float2half_rn(tile[tx][i]);
}

// ---------------- stage 4: feature generation (fp16, permuted layout) ----------------
__device__ __forceinline__ int PAD(int n) { return n + (n >> 4); }  // conflict-free smem

__global__ void __launch_bounds__(256) k_featgen(const float* __restrict__ x) {
    __shared__ float p[544];                 // p[n] = x[b,n] * s[n]
    int b = blockIdx.x, tid = threadIdx.x;
    for (int n = tid; n < 512; n += 256)
        p[PAD(n)] = x[(size_t)b * 512 + n] * g_s[n];
    __syncthreads();

    __half2 h[8];
    __half* dst;
    if (tid < 192) {
        // j = tid*16 .. +15 ; q = tid>>5, n0 = (tid&31)*16  (all same q)
        int q = tid >> 5;
        int n0 = (tid & 31) << 4;
        const float4* dq4 = (const float4*)(g_dq + q * 512 + n0);
#pragma unroll
        for (int c4 = 0; c4 < 4; c4++) {
            float4 d = dq4[c4];
            int nb = n0 + c4 * 4;
            float v0 = fmaxf(p[PAD(nb + 0)] + d.x, 0.f);
            float v1 = fmaxf(p[PAD(nb + 1)] + d.y, 0.f);
            float v2 = fmaxf(p[PAD(nb + 2)] + d.z, 0.f);
            float v3 = fmaxf(p[PAD(nb + 3)] + d.w, 0.f);
            h[c4 * 2 + 0] = __floats2half2_rn(v0, v1);
            h[c4 * 2 + 1] = __floats2half2_rn(v2, v3);
        }
        dst = g_feat + (size_t)b * K_TOT + tid * 16;
    } else {
        int m0 = (tid - 192) * 16;
        uint32_t pk[16];
        const uint4* gi = (const uint4*)(g_minidx + m0);
#pragma unroll
        for (int t = 0; t < 4; t++) { uint4 u = gi[t];
            pk[t*4+0]=u.x; pk[t*4+1]=u.y; pk[t*4+2]=u.z; pk[t*4+3]=u.w; }
#pragma unroll
        for (int c = 0; c < 16; c += 2) {
            float v[2];
#pragma unroll
            for (int u = 0; u < 2; u++) {
                uint32_t w2 = pk[c + u];
                int o1 = w2 & 0xFFFF, o2 = w2 >> 16;
                float a  = fmaxf(p[PAD(o1 & 511)] + g_dq[o1], 0.f);
                float bb = fmaxf(p[PAD(o2 & 511)] + g_dq[o2], 0.f);
                v[u] = fminf(a, bb);
            }
            h[c >> 1] = __floats2half2_rn(v[0], v[1]);
        }
        dst = g_feat + (size_t)b * K_TOT + 3072 + m0;
    }
    union { __half2 hh[8]; uint4 uu[2]; } out;
#pragma unroll
    for (int i = 0; i < 8; i++) out.hh[i] = h[i];
    uint4* d4 = (uint4*)dst;
    d4[0] = out.uu[0];
    d4[1] = out.uu[1];
}

// ---------------- stage 5: mma.sync fp16 GEMM, 128x128 tile, BK=64, 4-stage cp.async ----------------
// A = g_feat (row-major [8192,4096]);  B^T = g_wT (row-major [256,4096])  -> mma row.col
#define STAGE_BYTES 32768                  // A 16KB + B 16KB
#define GEMM_SMEM   (4 * STAGE_BYTES)      // 128 KB

__global__ void __launch_bounds__(256, 1) k_gemm(float* __restrict__ out,
                                                 const float* __restrict__ biases) {
    extern __shared__ __align__(1024) char smem[];
    uint32_t sb = smem_u32(smem);
    int tid = threadIdx.x, wid = tid >> 5, lid = tid & 31;
    int o0 = blockIdx.x * 128;   // output-col tile
    int r0 = blockIdx.y * 128;   // batch-row tile

    // warp tiling: 2 (M) x 4 (N): warp tile 64 (M) x 32 (N)
    int wm = (wid & 1) * 64;     // warp m offset within CTA tile
    int wn = (wid >> 1) * 32;    // warp n offset within CTA tile

    const char* Abase = (const char*)(g_feat + (size_t)r0 * K_TOT);
    const char* Bbase = (const char*)(g_wT + (size_t)o0 * K_TOT);

    auto issue = [&](int chunk, int stage) {
        uint32_t sa = sb + stage * STAGE_BYTES;
        uint32_t sB = sa + 16384;
        const char* Ag = Abase + chunk * 128;   // 64 halfs = 128 B per row
        const char* Bg = Bbase + chunk * 128;
#pragma unroll
        for (int t = 0; t < 4; t++) {
            int idx = tid + t * 256;            // 0..1023  (128 rows x 8 x 16B)
            int row = idx >> 3, jj = idx & 7;
            uint32_t off = row * 128 + 16 * (jj ^ (row & 7));   // XOR-128B swizzle
            const char* ga = Ag + (size_t)row * 8192 + jj * 16;
            const char* gb = Bg + (size_t)row * 8192 + jj * 16;
            asm volatile("cp.async.cg.shared.global [%0], [%1], 16;\n"
                         :: "r"(sa + off), "l"(ga));
            asm volatile("cp.async.cg.shared.global [%0], [%1], 16;\n"
                         :: "r"(sB + off), "l"(gb));
        }
    };

    // per-lane ldmatrix address constants
    int l7 = lid & 7, mi = lid >> 3;
    int a_row = wm + (mi & 1) * 8 + l7;          // within CTA tile
    int a_jc  = mi >> 1;                         // 0/1 within k16
    int b_row = wn + (mi >> 1) * 8 + l7;
    int b_jc  = mi & 1;

    float acc[4][4][4];
#pragma unroll
    for (int i = 0; i < 4; i++)
#pragma unroll
        for (int j = 0; j < 4; j++)
#pragma unroll
            for (int k = 0; k < 4; k++) acc[i][j][k] = 0.f;

    issue(0, 0); asm volatile("cp.async.commit_group;\n");
    issue(1, 1); asm volatile("cp.async.commit_group;\n");
    issue(2, 2); asm volatile("cp.async.commit_group;\n");

    for (int chunk = 0; chunk < 64; chunk++) {
        asm volatile("cp.async.wait_group 2;\n");
        __syncthreads();

        int stage = chunk & 3;
        uint32_t sA = sb + stage * STAGE_BYTES;
        uint32_t sBB = sA + 16384;

#pragma unroll
        for (int ks = 0; ks < 4; ks++) {        // 4 x k16 per BK=64 chunk
            uint32_t a[4][4];
#pragma unroll
            for (int mt = 0; mt < 4; mt++) {
                int r = a_row + mt * 16;
                uint32_t addr = sA + r * 128 + 16 * ((ks * 2 + a_jc) ^ (r & 7));
                asm volatile("ldmatrix.sync.aligned.m8n8.x4.shared.b16 {%0,%1,%2,%3}, [%4];"
                             : "=r"(a[mt][0]), "=r"(a[mt][1]), "=r"(a[mt][2]), "=r"(a[mt][3])
                             : "r"(addr));
            }
            uint32_t b[2][4];
#pragma unroll
            for (int nt = 0; nt < 2; nt++) {
                int r = b_row + nt * 16;
                uint32_t addr = sBB + r * 128 + 16 * ((ks * 2 + b_jc) ^ (r & 7));
                asm volatile("ldmatrix.sync.aligned.m8n8.x4.shared.b16 {%0,%1,%2,%3}, [%4];"
                             : "=r"(b[nt][0]), "=r"(b[nt][1]), "=r"(b[nt][2]), "=r"(b[nt][3])
                             : "r"(addr));
            }
#pragma unroll
            for (int mt = 0; mt < 4; mt++) {
#pragma unroll
                for (int j = 0; j < 4; j++) {
                    uint32_t b0 = b[j >> 1][(j & 1) * 2 + 0];
                    uint32_t b1 = b[j >> 1][(j & 1) * 2 + 1];
                    asm volatile(
                        "mma.sync.aligned.m16n8k16.row.col.f32.f16.f16.f32 "
                        "{%0,%1,%2,%3}, {%4,%5,%6,%7}, {%8,%9}, {%0,%1,%2,%3};"
                        : "+f"(acc[mt][j][0]), "+f"(acc[mt][j][1]),
                          "+f"(acc[mt][j][2]), "+f"(acc[mt][j][3])
                        : "r"(a[mt][0]), "r"(a[mt][1]), "r"(a[mt][2]), "r"(a[mt][3]),
                          "r"(b0), "r"(b1));
                }
            }
        }

        __syncthreads();
        int nxt = chunk + 3;
        if (nxt < 64) {
            issue(nxt, nxt & 3);
            asm volatile("cp.async.commit_group;\n");
        }
    }

    // epilogue: write accumulators + bias
    float bias = biases[0];
    int g = lid >> 2, t = lid & 3;
#pragma unroll
    for (int mt = 0; mt < 4; mt++) {
        int row = r0 + wm + mt * 16 + g;
#pragma unroll
        for (int j = 0; j < 4; j++) {
            int col = o0 + wn + j * 8 + t * 2;
            float2 v0 = make_float2(acc[mt][j][0] + bias, acc[mt][j][1] + bias);
            float2 v1 = make_float2(acc[mt][j][2] + bias, acc[mt][j][3] + bias);
            *(float2*)(out + (size_t)row * 256 + col)       = v0;
            *(float2*)(out + (size_t)(row + 8) * 256 + col) = v1;
        }
    }
}

// ---------------- launch ----------------
extern "C" void kernel_launch(void* const* d_in, const int* in_sizes, int n_in,
                              void* d_out, int out_size) {
    const float* x      = (const float*)d_in[0];
    const float* beta   = (const float*)d_in[1];
    const float* gamma  = (const float*)d_in[2];
    const float* w      = (const float*)d_in[3];
    const float* biases = (const float*)d_in[4];
    const void*  ci     = d_in[5];
    float* out = (float*)d_out;

    (void)in_sizes; (void)n_in; (void)out_size;

    k_stats<<<64, 512>>>(x);
    k_finalize<<<1, 512>>>(beta, gamma);
    k_packidx<<<1, 1024>>>(ci);
    k_wprep<<<dim3(128, 8), dim3(32, 8)>>>(w);
    k_featgen<<<B_ROWS, 256>>>(x);

    cudaFuncSetAttribute(k_gemm, cudaFuncAttributeMaxDynamicSharedMemorySize, GEMM_SMEM);
    k_gemm<<<dim3(2, 64), 256, GEMM_SMEM>>>(out, biases);
}

// round 6
// speedup vs baseline: 1.0529x; 1.0529x over previous
#include <cuda_runtime.h>
#include <cuda_fp16.h>
#include <cstdint>
#include <math.h>

// Problem dims
#define B_ROWS 8192
#define N_COLS 512
#define M_MIN  1024
#define OUT_N  256
#define K_TOT  4096   // 512*6 + 1024

// ---------------- device scratch (static, no allocation) ----------------
__device__ float g_psum[64 * 512];
__device__ float g_psumsq[64 * 512];
__device__ float g_s[512];
__device__ float g_dq[6 * 512];           // [q][n]
__device__ uint32_t g_minidx[M_MIN];      // packed (off2<<16)|off1, off = q*512+n
__device__ __align__(16) __half g_wT[(size_t)OUT_N * K_TOT];        // 2 MB  (B^T, [256,4096] K-major)
__device__ __align__(16) __half g_feat[(size_t)B_ROWS * K_TOT];     // 64 MB (A, [8192,4096] K-major)

__constant__ float QCOEF[5] = {-3.0f, -0.834f, -0.248f, 0.248f, 0.834f};

// ---------------- helpers ----------------
__device__ __forceinline__ uint32_t smem_u32(const void* p) {
    uint32_t a;
    asm("{ .reg .u64 t; cvta.to.shared.u64 t, %1; cvt.u32.u64 %0, t; }"
        : "=r"(a) : "l"(p));
    return a;
}

// ---------------- stage 1: column statistics (deterministic two-pass) ----------------
__global__ void __launch_bounds__(512) k_stats(const float* __restrict__ x) {
    int col = threadIdx.x;
    int rb  = blockIdx.x * 128;
    const float* xp = x + (size_t)rb * 512 + col;
    float s = 0.f, ss = 0.f;
#pragma unroll 8
    for (int r = 0; r < 128; r++) {
        float v = xp[(size_t)r * 512];
        s += v;
        ss = fmaf(v, v, ss);
    }
    g_psum[blockIdx.x * 512 + col]   = s;
    g_psumsq[blockIdx.x * 512 + col] = ss;
}

// ---------------- stage 2: finalize stats + pack min indices (merged, 1 block) ----------------
// chosen_index may arrive as int64 OR int32 (JAX x64-disabled silently downcasts).
// Column 0 is arange(M): int32-view element 10 == 1 iff int64, == 2 iff int32.
__global__ void __launch_bounds__(1024) k_finalize(const float* __restrict__ beta,
                                                   const float* __restrict__ gamma,
                                                   const void* __restrict__ ci_raw) {
    int tid = threadIdx.x;
    if (tid < 512) {
        int n = tid;
        float s = 0.f, ss = 0.f;
        for (int b = 0; b < 64; b++) {       // fixed order -> deterministic
            s  += g_psum[b * 512 + n];
            ss += g_psumsq[b * 512 + n];
        }
        float mean = s * (1.f / 8192.f);
        float var  = ss * (1.f / 8192.f) - mean * mean;
        float sc   = gamma[n] / sqrtf(var + 0.001f);
        float c    = beta[n] - mean * sc;    // normed = sc*x + c
        g_s[n]  = sc;
        g_dq[n] = c;                          // q = 0 (base relu)
#pragma unroll
        for (int q = 0; q < 5; q++)
            g_dq[(q + 1) * 512 + n] = c + beta[n] - gamma[n] * fmaf(QCOEF[q], var, mean);
    }
    {
        int m = tid;
        const int* p32 = (const int*)ci_raw;
        bool is64 = (p32[10] == 1) && (p32[11] == 0);
        uint32_t n1, q1, n2, q2;
        if (is64) {
            const long long* e = (const long long*)ci_raw + (size_t)m * 5;
            n1 = (uint32_t)e[1]; q1 = (uint32_t)e[2];
            n2 = (uint32_t)e[3]; q2 = (uint32_t)e[4];
        } else {
            const int* e = p32 + (size_t)m * 5;
            n1 = (uint32_t)e[1]; q1 = (uint32_t)e[2];
            n2 = (uint32_t)e[3]; q2 = (uint32_t)e[4];
        }
        g_minidx[m] = ((q2 * 512u + n2) << 16) | (q1 * 512u + n1);
    }
}

// ---------------- stage 3: w -> wT fp16, K-permuted (j = q*512+n for j<3072) ----------------
__global__ void __launch_bounds__(256) k_wprep(const float* __restrict__ w) {
    __shared__ float tile[32][33];
    int j0 = blockIdx.x * 32, o0 = blockIdx.y * 32;
    int tx = threadIdx.x, ty = threadIdx.y;
    for (int i = ty; i < 32; i += 8) {
        int j = j0 + i;
        int k = (j < 3072) ? ((j & 511) * 6 + (j >> 9)) : j;   // back to original row order
        tile[i][tx] = w[(size_t)k * 256 + o0 + tx];
    }
    __syncthreads();
    for (int i = ty; i < 32; i += 8)
        g_wT[(size_t)(o0 + i) * K_TOT + j0 + tx] = __float2half_rn(tile[tx][i]);
}

// ---------------- stage 4: feature generation (fp16, permuted layout, 4 rows/block) ----------------
__device__ __forceinline__ int PAD(int n) { return n + (n >> 4); }  // conflict-free smem

__global__ void __launch_bounds__(256) k_featgen(const float* __restrict__ x) {
    __shared__ float p[4][544];              // p[r][n] = x[b0+r,n] * s[n]
    int b0 = blockIdx.x * 4, tid = threadIdx.x;
    for (int i = tid; i < 2048; i += 256) {
        int r = i >> 9, n = i & 511;
        p[r][PAD(n)] = x[(size_t)(b0 + r) * 512 + n] * g_s[n];
    }
    __syncthreads();

    if (tid < 192) {
        // j = tid*16 .. +15 ; q = tid>>5, n0 = (tid&31)*16  (all same q)
        int q = tid >> 5;
        int n0 = (tid & 31) << 4;
        float4 d[4];
        const float4* dq4 = (const float4*)(g_dq + q * 512 + n0);
#pragma unroll
        for (int c4 = 0; c4 < 4; c4++) d[c4] = dq4[c4];
#pragma unroll
        for (int r = 0; r < 4; r++) {
            union { __half2 hh[8]; uint4 uu[2]; } out;
#pragma unroll
            for (int c4 = 0; c4 < 4; c4++) {
                int nb = n0 + c4 * 4;
                float v0 = fmaxf(p[r][PAD(nb + 0)] + d[c4].x, 0.f);
                float v1 = fmaxf(p[r][PAD(nb + 1)] + d[c4].y, 0.f);
                float v2 = fmaxf(p[r][PAD(nb + 2)] + d[c4].z, 0.f);
                float v3 = fmaxf(p[r][PAD(nb + 3)] + d[c4].w, 0.f);
                out.hh[c4 * 2 + 0] = __floats2half2_rn(v0, v1);
                out.hh[c4 * 2 + 1] = __floats2half2_rn(v2, v3);
            }
            uint4* d4 = (uint4*)(g_feat + (size_t)(b0 + r) * K_TOT + tid * 16);
            d4[0] = out.uu[0];
            d4[1] = out.uu[1];
        }
    } else {
        int m0 = (tid - 192) * 16;
        uint32_t pk[16];
        const uint4* gi = (const uint4*)(g_minidx + m0);
#pragma unroll
        for (int t = 0; t < 4; t++) { uint4 u = gi[t];
            pk[t*4+0]=u.x; pk[t*4+1]=u.y; pk[t*4+2]=u.z; pk[t*4+3]=u.w; }
#pragma unroll
        for (int r = 0; r < 4; r++) {
            union { __half2 hh[8]; uint4 uu[2]; } out;
#pragma unroll
            for (int c = 0; c < 16; c += 2) {
                float v[2];
#pragma unroll
                for (int u = 0; u < 2; u++) {
                    uint32_t w2 = pk[c + u];
                    int o1 = w2 & 0xFFFF, o2 = w2 >> 16;
                    float a  = fmaxf(p[r][PAD(o1 & 511)] + g_dq[o1], 0.f);
                    float bb = fmaxf(p[r][PAD(o2 & 511)] + g_dq[o2], 0.f);
                    v[u] = fminf(a, bb);
                }
                out.hh[c >> 1] = __floats2half2_rn(v[0], v[1]);
            }
            uint4* d4 = (uint4*)(g_feat + (size_t)(b0 + r) * K_TOT + 3072 + m0);
            d4[0] = out.uu[0];
            d4[1] = out.uu[1];
        }
    }
}

// ---------------- stage 5: mma.sync fp16 GEMM, BM=64 x BN=256, BK=64, 4-stage cp.async ----------------
// A = g_feat (row-major [8192,4096]);  B^T = g_wT (row-major [256,4096])  -> mma row.col
// grid (128): each CTA does 64 batch rows x ALL 256 out cols -> feat read ONCE from DRAM.
#define A_STAGE_BYTES 8192                 // 64 rows x 128 B
#define B_STAGE_BYTES 32768                // 256 rows x 128 B
#define STAGE_BYTES   (A_STAGE_BYTES + B_STAGE_BYTES)   // 40960
#define GEMM_SMEM     (4 * STAGE_BYTES)    // 163840

__global__ void __launch_bounds__(256, 1) k_gemm(float* __restrict__ out,
                                                 const float* __restrict__ biases) {
    extern __shared__ __align__(1024) char smem[];
    uint32_t sb = smem_u32(smem);
    int tid = threadIdx.x, wid = tid >> 5, lid = tid & 31;
    int r0 = blockIdx.x * 64;    // batch-row tile

    // warp tiling: 2 (M) x 4 (N): warp tile 32 (M) x 64 (N)
    int wm = (wid & 1) * 32;
    int wn = (wid >> 1) * 64;

    const char* Abase = (const char*)(g_feat + (size_t)r0 * K_TOT);
    const char* Bbase = (const char*)g_wT;

    auto issue = [&](int chunk, int stage) {
        uint32_t sa = sb + stage * STAGE_BYTES;
        uint32_t sB = sa + A_STAGE_BYTES;
        const char* Ag = Abase + chunk * 128;   // 64 halfs = 128 B per row
        const char* Bg = Bbase + chunk * 128;
        {   // A: 512 x 16B, t = 0..1
#pragma unroll
            for (int t = 0; t < 2; t++) {
                int idx = tid + t * 256;        // 0..511
                int row = idx >> 3, jj = idx & 7;
                uint32_t off = row * 128 + 16 * (jj ^ (row & 7));
                const char* ga = Ag + (size_t)row * 8192 + jj * 16;
                asm volatile("cp.async.cg.shared.global [%0], [%1], 16;\n"
                             :: "r"(sa + off), "l"(ga));
            }
        }
        {   // B: 2048 x 16B, t = 0..7
#pragma unroll
            for (int t = 0; t < 8; t++) {
                int idx = tid + t * 256;        // 0..2047
                int row = idx >> 3, jj = idx & 7;
                uint32_t off = row * 128 + 16 * (jj ^ (row & 7));
                const char* gb = Bg + (size_t)row * 8192 + jj * 16;
                asm volatile("cp.async.cg.shared.global [%0], [%1], 16;\n"
                             :: "r"(sB + off), "l"(gb));
            }
        }
    };

    // per-lane ldmatrix address constants
    int l7 = lid & 7, mi = lid >> 3;
    int a_row = wm + (mi & 1) * 8 + l7;
    int a_jc  = mi >> 1;                     // 0/1 within k16
    int b_row = wn + (mi >> 1) * 8 + l7;
    int b_jc  = mi & 1;

    float acc[2][8][4];
#pragma unroll
    for (int i = 0; i < 2; i++)
#pragma unroll
        for (int j = 0; j < 8; j++)
#pragma unroll
            for (int k = 0; k < 4; k++) acc[i][j][k] = 0.f;

    issue(0, 0); asm volatile("cp.async.commit_group;\n");
    issue(1, 1); asm volatile("cp.async.commit_group;\n");
    issue(2, 2); asm volatile("cp.async.commit_group;\n");

    for (int chunk = 0; chunk < 64; chunk++) {
        asm volatile("cp.async.wait_group 2;\n");
        __syncthreads();

        int stage = chunk & 3;
        uint32_t sA = sb + stage * STAGE_BYTES;
        uint32_t sBB = sA + A_STAGE_BYTES;

#pragma unroll
        for (int ks = 0; ks < 4; ks++) {        // 4 x k16 per BK=64 chunk
            uint32_t a[2][4];
#pragma unroll
            for (int mt = 0; mt < 2; mt++) {
                int r = a_row + mt * 16;
                uint32_t addr = sA + r * 128 + 16 * ((ks * 2 + a_jc) ^ (r & 7));
                asm volatile("ldmatrix.sync.aligned.m8n8.x4.shared.b16 {%0,%1,%2,%3}, [%4];"
                             : "=r"(a[mt][0]), "=r"(a[mt][1]), "=r"(a[mt][2]), "=r"(a[mt][3])
                             : "r"(addr));
            }
            uint32_t b[4][4];
#pragma unroll
            for (int nt = 0; nt < 4; nt++) {
                int r = b_row + nt * 16;
                uint32_t addr = sBB + r * 128 + 16 * ((ks * 2 + b_jc) ^ (r & 7));
                asm volatile("ldmatrix.sync.aligned.m8n8.x4.shared.b16 {%0,%1,%2,%3}, [%4];"
                             : "=r"(b[nt][0]), "=r"(b[nt][1]), "=r"(b[nt][2]), "=r"(b[nt][3])
                             : "r"(addr));
            }
#pragma unroll
            for (int mt = 0; mt < 2; mt++) {
#pragma unroll
                for (int j = 0; j < 8; j++) {
                    uint32_t b0 = b[j >> 1][(j & 1) * 2 + 0];
                    uint32_t b1 = b[j >> 1][(j & 1) * 2 + 1];
                    asm volatile(
                        "mma.sync.aligned.m16n8k16.row.col.f32.f16.f16.f32 "
                        "{%0,%1,%2,%3}, {%4,%5,%6,%7}, {%8,%9}, {%0,%1,%2,%3};"
                        : "+f"(acc[mt][j][0]), "+f"(acc[mt][j][1]),
                          "+f"(acc[mt][j][2]), "+f"(acc[mt][j][3])
                        : "r"(a[mt][0]), "r"(a[mt][1]), "r"(a[mt][2]), "r"(a[mt][3]),
                          "r"(b0), "r"(b1));
                }
            }
        }

        __syncthreads();
        int nxt = chunk + 3;
        if (nxt < 64) {
            issue(nxt, nxt & 3);
            asm volatile("cp.async.commit_group;\n");
        }
    }

    // epilogue: write accumulators + bias
    float bias = biases[0];
    int g = lid >> 2, t = lid & 3;
#pragma unroll
    for (int mt = 0; mt < 2; mt++) {
        int row = r0 + wm + mt * 16 + g;
#pragma unroll
        for (int j = 0; j < 8; j++) {
            int col = wn + j * 8 + t * 2;
            float2 v0 = make_float2(acc[mt][j][0] + bias, acc[mt][j][1] + bias);
            float2 v1 = make_float2(acc[mt][j][2] + bias, acc[mt][j][3] + bias);
            *(float2*)(out + (size_t)row * 256 + col)       = v0;
            *(float2*)(out + (size_t)(row + 8) * 256 + col) = v1;
        }
    }
}

// ---------------- launch ----------------
extern "C" void kernel_launch(void* const* d_in, const int* in_sizes, int n_in,
                              void* d_out, int out_size) {
    const float* x      = (const float*)d_in[0];
    const float* beta   = (const float*)d_in[1];
    const float* gamma  = (const float*)d_in[2];
    const float* w      = (const float*)d_in[3];
    const float* biases = (const float*)d_in[4];
    const void*  ci     = d_in[5];
    float* out = (float*)d_out;

    (void)in_sizes; (void)n_in; (void)out_size;

    k_stats<<<64, 512>>>(x);
    k_finalize<<<1, 1024>>>(beta, gamma, ci);
    k_wprep<<<dim3(128, 8), dim3(32, 8)>>>(w);
    k_featgen<<<2048, 256>>>(x);

    cudaFuncSetAttribute(k_gemm, cudaFuncAttributeMaxDynamicSharedMemorySize, GEMM_SMEM);
    k_gemm<<<128, 256, GEMM_SMEM>>>(out, biases);
}

// round 7
// speedup vs baseline: 1.1700x; 1.1112x over previous
#include <cuda_runtime.h>
#include <cuda_fp16.h>
#include <cstdint>
#include <math.h>

// Problem dims
#define B_ROWS 8192
#define N_COLS 512
#define M_MIN  1024
#define OUT_N  256
#define K_TOT  4096   // 512*6 + 1024

// ---------------- device scratch (static, no allocation) ----------------
__device__ float g_psum[64 * 512];
__device__ float g_psumsq[64 * 512];
__device__ float g_s[512];
__device__ float g_dq[6 * 512];           // [q][n]  (q=0 base, q=1..5 branches)
__device__ uint32_t g_minidx[M_MIN];      // packed (off2<<16)|off1, off = q*512+n (< 3072)
__device__ __align__(16) __half g_wT[(size_t)OUT_N * K_TOT];   // 2 MB (B^T, [256,4096] K-major, K-permuted)

__constant__ float QCOEF[5] = {-3.0f, -0.834f, -0.248f, 0.248f, 0.834f};

// ---------------- helpers ----------------
__device__ __forceinline__ uint32_t smem_u32(const void* p) {
    uint32_t a;
    asm("{ .reg .u64 t; cvta.to.shared.u64 t, %1; cvt.u32.u64 %0, t; }"
        : "=r"(a) : "l"(p));
    return a;
}

// ---------------- stage 1: column statistics (deterministic two-pass) ----------------
__global__ void __launch_bounds__(512) k_stats(const float* __restrict__ x) {
    int col = threadIdx.x;
    int rb  = blockIdx.x * 128;
    const float* xp = x + (size_t)rb * 512 + col;
    float s = 0.f, ss = 0.f;
#pragma unroll 8
    for (int r = 0; r < 128; r++) {
        float v = xp[(size_t)r * 512];
        s += v;
        ss = fmaf(v, v, ss);
    }
    g_psum[blockIdx.x * 512 + col]   = s;
    g_psumsq[blockIdx.x * 512 + col] = ss;
}

// ---------------- stage 2: finalize stats + pack min indices (merged, 1 block) ----------------
// chosen_index may arrive as int64 OR int32 (JAX x64-disabled silently downcasts).
// Column 0 is arange(M): int32-view element 10 == 1 iff int64, == 2 iff int32.
__global__ void __launch_bounds__(1024) k_finalize(const float* __restrict__ beta,
                                                   const float* __restrict__ gamma,
                                                   const void* __restrict__ ci_raw) {
    int tid = threadIdx.x;
    if (tid < 512) {
        int n = tid;
        float s = 0.f, ss = 0.f;
        for (int b = 0; b < 64; b++) {       // fixed order -> deterministic
            s  += g_psum[b * 512 + n];
            ss += g_psumsq[b * 512 + n];
        }
        float mean = s * (1.f / 8192.f);
        float var  = ss * (1.f / 8192.f) - mean * mean;
        float sc   = gamma[n] / sqrtf(var + 0.001f);
        float c    = beta[n] - mean * sc;    // normed = sc*x + c
        g_s[n]  = sc;
        g_dq[n] = c;                          // q = 0 (base relu)
#pragma unroll
        for (int q = 0; q < 5; q++)
            g_dq[(q + 1) * 512 + n] = c + beta[n] - gamma[n] * fmaf(QCOEF[q], var, mean);
    }
    {
        int m = tid;
        const int* p32 = (const int*)ci_raw;
        bool is64 = (p32[10] == 1) && (p32[11] == 0);
        uint32_t n1, q1, n2, q2;
        if (is64) {
            const long long* e = (const long long*)ci_raw + (size_t)m * 5;
            n1 = (uint32_t)e[1]; q1 = (uint32_t)e[2];
            n2 = (uint32_t)e[3]; q2 = (uint32_t)e[4];
        } else {
            const int* e = p32 + (size_t)m * 5;
            n1 = (uint32_t)e[1]; q1 = (uint32_t)e[2];
            n2 = (uint32_t)e[3]; q2 = (uint32_t)e[4];
        }
        g_minidx[m] = ((q2 * 512u + n2) << 16) | (q1 * 512u + n1);
    }
}

// ---------------- stage 3: w -> wT fp16, K-permuted (j = q*512+n for j<3072) ----------------
__global__ void __launch_bounds__(256) k_wprep(const float* __restrict__ w) {
    __shared__ float tile[32][33];
    int j0 = blockIdx.x * 32, o0 = blockIdx.y * 32;
    int tx = threadIdx.x, ty = threadIdx.y;
    for (int i = ty; i < 32; i += 8) {
        int j = j0 + i;
        int k = (j < 3072) ? ((j & 511) * 6 + (j >> 9)) : j;   // back to original row order
        tile[i][tx] = w[(size_t)k * 256 + o0 + tx];
    }
    __syncthreads();
    for (int i = ty; i < 32; i += 8)
        g_wT[(size_t)(o0 + i) * K_TOT + j0 + tx] = __float2half_rn(tile[tx][i]);
}

// ---------------- stage 4: FUSED featgen + GEMM ----------------
// BM=64, BN=256, BK=64, grid=128 (one wave). A tile synthesized in smem from
// p[row][n] = x*s (fp16, stride 520 halfs for conflict-free banks); B via cp.async.
#define A_SLOT_BYTES  8192                      // 64 rows x 128 B
#define B_STAGE_BYTES 32768                     // 256 rows x 128 B
#define B_OFF   (2 * A_SLOT_BYTES)              // 16384
#define P_OFF   (B_OFF + 4 * B_STAGE_BYTES)     // 147456
#define P_STRIDE 520                            // halfs per p row (pad 8 -> 4-bank shift/row)
#define GEMM_SMEM (P_OFF + 64 * P_STRIDE * 2)   // 147456 + 66560 = 214016

__global__ void __launch_bounds__(256) k_gemm(float* __restrict__ out,
                                              const float* __restrict__ x,
                                              const float* __restrict__ biases) {
    extern __shared__ __align__(1024) char smem[];
    uint32_t sb = smem_u32(smem);
    __half* p_sh = (__half*)(smem + P_OFF);
    int tid = threadIdx.x, wid = tid >> 5, lid = tid & 31;
    int r0 = blockIdx.x * 64;    // batch-row tile

    // warp tiling: 2 (M) x 4 (N): warp tile 32 (M) x 64 (N)
    int wm = (wid & 1) * 32;
    int wn = (wid >> 1) * 64;

    const char* Bbase = (const char*)g_wT;

    auto issueB = [&](int chunk, int stage) {
        uint32_t sB = sb + B_OFF + stage * B_STAGE_BYTES;
        const char* Bg = Bbase + chunk * 128;
#pragma unroll
        for (int t = 0; t < 8; t++) {
            int idx = tid + t * 256;            // 0..2047
            int row = idx >> 3, jj = idx & 7;
            uint32_t off = row * 128 + 16 * (jj ^ (row & 7));
            const char* gb = Bg + (size_t)row * 8192 + jj * 16;
            asm volatile("cp.async.cg.shared.global [%0], [%1], 16;\n"
                         :: "r"(sB + off), "l"(gb));
        }
    };

    // ---- A producer: synthesize 64x64 fp16 tile for K-chunk into A slot ----
    // unit mapping: jj = tid&7 (16B group), rbase = tid>>3, rows rbase + {0,32}
    int jj = tid & 7, rbase = tid >> 3;
    auto produceA = [&](int chunk, int slot) {
        char* sa = smem + slot * A_SLOT_BYTES;
        if (chunk < 48) {
            int q = chunk >> 3;
            int nc = (chunk & 7) * 64 + jj * 8;          // p column base (0..511)
            const float4* dd = (const float4*)(g_dq + q * 512 + nc);
            float4 da = dd[0], db = dd[1];
#pragma unroll
            for (int t = 0; t < 2; t++) {
                int row = rbase + t * 32;
                const __half2* pr = (const __half2*)(p_sh + row * P_STRIDE + nc);
                __half2 h0 = pr[0], h1 = pr[1], h2 = pr[2], h3 = pr[3];
                float2 f0 = __half22float2(h0), f1 = __half22float2(h1);
                float2 f2 = __half22float2(h2), f3 = __half22float2(h3);
                __half2 o0 = __floats2half2_rn(fmaxf(f0.x + da.x, 0.f), fmaxf(f0.y + da.y, 0.f));
                __half2 o1 = __floats2half2_rn(fmaxf(f1.x + da.z, 0.f), fmaxf(f1.y + da.w, 0.f));
                __half2 o2 = __floats2half2_rn(fmaxf(f2.x + db.x, 0.f), fmaxf(f2.y + db.y, 0.f));
                __half2 o3 = __floats2half2_rn(fmaxf(f3.x + db.z, 0.f), fmaxf(f3.y + db.w, 0.f));
                union { __half2 h[4]; uint4 u; } o; o.h[0]=o0; o.h[1]=o1; o.h[2]=o2; o.h[3]=o3;
                *(uint4*)(sa + row * 128 + 16 * (jj ^ (row & 7))) = o.u;
            }
        } else {
            int m0 = (chunk - 48) * 64 + jj * 8;
            uint4 pa = *(const uint4*)(g_minidx + m0);
            uint4 pb = *(const uint4*)(g_minidx + m0 + 4);
            uint32_t pk[8] = {pa.x, pa.y, pa.z, pa.w, pb.x, pb.y, pb.z, pb.w};
            int c1[8], c2[8];
            float d1[8], d2[8];
#pragma unroll
            for (int i = 0; i < 8; i++) {
                int o1 = pk[i] & 0xFFFF, o2 = pk[i] >> 16;
                d1[i] = g_dq[o1]; d2[i] = g_dq[o2];
                c1[i] = o1 & 511; c2[i] = o2 & 511;
            }
#pragma unroll
            for (int t = 0; t < 2; t++) {
                int row = rbase + t * 32;
                const __half* pr = p_sh + row * P_STRIDE;
                union { __half2 h[4]; uint4 u; } o;
#pragma unroll
                for (int i = 0; i < 4; i++) {
                    float va = fminf(fmaxf(__half2float(pr[c1[2*i]])   + d1[2*i],   0.f),
                                     fmaxf(__half2float(pr[c2[2*i]])   + d2[2*i],   0.f));
                    float vb = fminf(fmaxf(__half2float(pr[c1[2*i+1]]) + d1[2*i+1], 0.f),
                                     fmaxf(__half2float(pr[c2[2*i+1]]) + d2[2*i+1], 0.f));
                    o.h[i] = __floats2half2_rn(va, vb);
                }
                *(uint4*)(sa + row * 128 + 16 * (jj ^ (row & 7))) = o.u;
            }
        }
    };

    // ---- prefetch B ----
    issueB(0, 0); asm volatile("cp.async.commit_group;\n");
    issueB(1, 1); asm volatile("cp.async.commit_group;\n");
    issueB(2, 2); asm volatile("cp.async.commit_group;\n");

    // ---- build p[64][512]: p = x * s (fp16) ----
    {
        int grp = tid & 63;        // 8-float group within row
        int rt  = tid >> 6;        // 0..3
        const float4* s4 = (const float4*)(g_s + grp * 8);
        float4 sa4 = s4[0], sb4 = s4[1];
#pragma unroll
        for (int t = 0; t < 16; t++) {
            int row = rt + t * 4;
            const float4* xr = (const float4*)(x + (size_t)(r0 + row) * 512 + grp * 8);
            float4 xa = xr[0], xb = xr[1];
            union { __half2 h[4]; uint4 u; } o;
            o.h[0] = __floats2half2_rn(xa.x * sa4.x, xa.y * sa4.y);
            o.h[1] = __floats2half2_rn(xa.z * sa4.z, xa.w * sa4.w);
            o.h[2] = __floats2half2_rn(xb.x * sb4.x, xb.y * sb4.y);
            o.h[3] = __floats2half2_rn(xb.z * sb4.z, xb.w * sb4.w);
            *(uint4*)(p_sh + row * P_STRIDE + grp * 8) = o.u;
        }
    }
    __syncthreads();
    produceA(0, 0);                 // first A tile

    // per-lane ldmatrix address constants
    int l7 = lid & 7, mi = lid >> 3;
    int a_row = wm + (mi & 1) * 8 + l7;
    int a_jc  = mi >> 1;            // 0/1 within k16
    int b_row = wn + (mi >> 1) * 8 + l7;
    int b_jc  = mi & 1;

    float acc[2][8][4];
#pragma unroll
    for (int i = 0; i < 2; i++)
#pragma unroll
        for (int j = 0; j < 8; j++)
#pragma unroll
            for (int k = 0; k < 4; k++) acc[i][j][k] = 0.f;

    for (int chunk = 0; chunk < 64; chunk++) {
        asm volatile("cp.async.wait_group 2;\n");
        __syncthreads();            // B(chunk) + A(chunk) visible; prev reads done

        uint32_t sA  = sb + (chunk & 1) * A_SLOT_BYTES;
        uint32_t sBB = sb + B_OFF + (chunk & 3) * B_STAGE_BYTES;

#pragma unroll
        for (int ks = 0; ks < 4; ks++) {        // 4 x k16 per BK=64 chunk
            uint32_t a[2][4];
#pragma unroll
            for (int mt = 0; mt < 2; mt++) {
                int r = a_row + mt * 16;
                uint32_t addr = sA + r * 128 + 16 * ((ks * 2 + a_jc) ^ (r & 7));
                asm volatile("ldmatrix.sync.aligned.m8n8.x4.shared.b16 {%0,%1,%2,%3}, [%4];"
                             : "=r"(a[mt][0]), "=r"(a[mt][1]), "=r"(a[mt][2]), "=r"(a[mt][3])
                             : "r"(addr));
            }
            uint32_t b[4][4];
#pragma unroll
            for (int nt = 0; nt < 4; nt++) {
                int r = b_row + nt * 16;
                uint32_t addr = sBB + r * 128 + 16 * ((ks * 2 + b_jc) ^ (r & 7));
                asm volatile("ldmatrix.sync.aligned.m8n8.x4.shared.b16 {%0,%1,%2,%3}, [%4];"
                             : "=r"(b[nt][0]), "=r"(b[nt][1]), "=r"(b[nt][2]), "=r"(b[nt][3])
                             : "r"(addr));
            }
#pragma unroll
            for (int mt = 0; mt < 2; mt++) {
#pragma unroll
                for (int j = 0; j < 8; j++) {
                    uint32_t b0 = b[j >> 1][(j & 1) * 2 + 0];
                    uint32_t b1 = b[j >> 1][(j & 1) * 2 + 1];
                    asm volatile(
                        "mma.sync.aligned.m16n8k16.row.col.f32.f16.f16.f32 "
                        "{%0,%1,%2,%3}, {%4,%5,%6,%7}, {%8,%9}, {%0,%1,%2,%3};"
                        : "+f"(acc[mt][j][0]), "+f"(acc[mt][j][1]),
                          "+f"(acc[mt][j][2]), "+f"(acc[mt][j][3])
                        : "r"(a[mt][0]), "r"(a[mt][1]), "r"(a[mt][2]), "r"(a[mt][3]),
                          "r"(b0), "r"(b1));
                }
            }
        }

        if (chunk + 3 < 64) {
            issueB(chunk + 3, (chunk + 3) & 3);
            asm volatile("cp.async.commit_group;\n");
        }
        if (chunk + 1 < 64)
            produceA(chunk + 1, (chunk + 1) & 1);   // other slot; prev reads synced above
    }

    // epilogue: write accumulators + bias
    float bias = biases[0];
    int g = lid >> 2, t = lid & 3;
#pragma unroll
    for (int mt = 0; mt < 2; mt++) {
        int row = r0 + wm + mt * 16 + g;
#pragma unroll
        for (int j = 0; j < 8; j++) {
            int col = wn + j * 8 + t * 2;
            float2 v0 = make_float2(acc[mt][j][0] + bias, acc[mt][j][1] + bias);
            float2 v1 = make_float2(acc[mt][j][2] + bias, acc[mt][j][3] + bias);
            *(float2*)(out + (size_t)row * 256 + col)       = v0;
            *(float2*)(out + (size_t)(row + 8) * 256 + col) = v1;
        }
    }
}

// ---------------- launch ----------------
extern "C" void kernel_launch(void* const* d_in, const int* in_sizes, int n_in,
                              void* d_out, int out_size) {
    const float* x      = (const float*)d_in[0];
    const float* beta   = (const float*)d_in[1];
    const float* gamma  = (const float*)d_in[2];
    const float* w      = (const float*)d_in[3];
    const float* biases = (const float*)d_in[4];
    const void*  ci     = d_in[5];
    float* out = (float*)d_out;

    (void)in_sizes; (void)n_in; (void)out_size;

    k_stats<<<64, 512>>>(x);
    k_finalize<<<1, 1024>>>(beta, gamma, ci);
    k_wprep<<<dim3(128, 8), dim3(32, 8)>>>(w);

    cudaFuncSetAttribute(k_gemm, cudaFuncAttributeMaxDynamicSharedMemorySize, GEMM_SMEM);
    k_gemm<<<128, 256, GEMM_SMEM>>>(out, x, biases);
}